// round 6
// baseline (speedup 1.0000x reference)
#include <cuda_runtime.h>
#include <cstdint>

// ---------------- problem constants ----------------
#define D_IN   2048
#define D_H    512
#define BN_EPS 1e-3f

// ---------------- GEMM tiling ----------------
#define BM 128
#define BN 256
#define KC 128                      // k elems (s8) per chunk
#define NCHUNK (D_IN / KC)          // 16
#define B_STAGE (BN * KC)           // 32768
#define SMEM_DYN (3 * B_STAGE)      // 98304

// ---------------- device scratch ----------------
__device__ __align__(16) signed char g_Wq[(size_t)D_H * D_IN];    // [n][k] s8 +-1
__device__ float g_alpha[D_H];
__device__ float g_cbias[D_H];

// ---------------- PTX helpers ----------------
__device__ __forceinline__ uint32_t smem_u32(const void* p) {
    return (uint32_t)__cvta_generic_to_shared(p);
}
__device__ __forceinline__ void cp16(uint32_t s, const void* g) {
    asm volatile("cp.async.cg.shared.global [%0], [%1], 16;" :: "r"(s), "l"(g));
}
__device__ __forceinline__ void cp_commit() {
    asm volatile("cp.async.commit_group;" ::: "memory");
}
template <int N>
__device__ __forceinline__ void cp_wait() {
    asm volatile("cp.async.wait_group %0;" :: "n"(N) : "memory");
}
__device__ __forceinline__ void ldsm4(uint32_t* r, uint32_t addr) {
    asm volatile("ldmatrix.sync.aligned.m8n8.x4.shared.b16 {%0,%1,%2,%3}, [%4];"
                 : "=r"(r[0]), "=r"(r[1]), "=r"(r[2]), "=r"(r[3]) : "r"(addr));
}
__device__ __forceinline__ void mma_s8(int* c, const uint32_t* a,
                                       uint32_t b0, uint32_t b1) {
    asm volatile(
        "mma.sync.aligned.m16n8k32.row.col.s32.s8.s8.s32 "
        "{%0,%1,%2,%3}, {%4,%5,%6,%7}, {%8,%9}, {%0,%1,%2,%3};"
        : "+r"(c[0]), "+r"(c[1]), "+r"(c[2]), "+r"(c[3])
        : "r"(a[0]), "r"(a[1]), "r"(a[2]), "r"(a[3]), "r"(b0), "r"(b1));
}
__device__ __forceinline__ uint32_t prmt(uint32_t a, uint32_t b, uint32_t sel) {
    uint32_t d;
    asm("prmt.b32 %0, %1, %2, %3;" : "=r"(d) : "r"(a), "r"(b), "r"(sel));
    return d;
}
// pack signs of 4 fp32 into 4 s8 (+1 / -1) via PRMT sign-replicate
__device__ __forceinline__ uint32_t pk4(uint4 u) {
    uint32_t s01 = prmt(u.x, u.y, 0x00FBu);
    uint32_t s23 = prmt(u.z, u.w, 0x00FBu);
    return prmt(s01, s23, 0x5410u) | 0x01010101u;
}

// ---------------- prep: W transpose + sign + BN fold ----------------
__global__ __launch_bounds__(256)
void qdbn_prep_kernel(const float* __restrict__ W,
                      const float* __restrict__ b,
                      const float* __restrict__ beta,
                      const float* __restrict__ mean,
                      const float* __restrict__ var) {
    __shared__ signed char tile[32][33];
    const int n0 = blockIdx.x * 32;
    const int k0 = blockIdx.y * 32;
    const int tx = threadIdx.x;   // 32
    const int ty = threadIdx.y;   // 8

    #pragma unroll
    for (int i = 0; i < 32; i += 8) {
        float w = W[(size_t)(k0 + ty + i) * D_H + (n0 + tx)];
        tile[ty + i][tx] = (w >= 0.0f) ? 1 : -1;
    }
    __syncthreads();
    #pragma unroll
    for (int i = 0; i < 32; i += 8) {
        g_Wq[(size_t)(n0 + ty + i) * D_IN + (k0 + tx)] = tile[tx][ty + i];
    }

    if (blockIdx.x == 0 && blockIdx.y == 0) {
        int t = ty * 32 + tx;
        #pragma unroll
        for (int idx = t; idx < D_H; idx += 256) {
            float inv = rsqrtf(var[idx] + BN_EPS);
            g_alpha[idx] = inv;
            g_cbias[idx] = (b[idx] - mean[idx]) * inv + beta[idx];
        }
    }
}

// ---------------- fused GEMM: binarize-X + s8 IMMA + BN ----------------
// CTA 128(M) x 256(N), 512 threads = 16 warps as 4(M) x 4(N) -> warp 64.. 32x64.
// A: fp32 X loaded straight into MMA fragments (LDG.128 + prmt pack), NO smem.
//    One k-step-ahead register prefetch (global loads are barrier-free).
// B: s8 from g_Wq via cp.async, 3-stage smem (rows 128B, granule ^ (row&7)).
__global__ __launch_bounds__(512, 1)
void qdbn_fused_kernel(const float* __restrict__ X, float* __restrict__ out) {
    extern __shared__ char dyn_smem[];
    const uint32_t sB0 = smem_u32(dyn_smem);

    const int tid  = threadIdx.x;
    const int wid  = tid >> 5;
    const int lane = tid & 31;
    const int m0 = blockIdx.y * BM;
    const int n0 = blockIdx.x * BN;
    const int wm = (wid >> 2) * 32;   // warp M offset (4 rows of warps)
    const int wn = (wid & 3) * 64;    // warp N offset (4 cols of warps)

    const int g  = lane >> 2;         // fragment row group 0..7
    const int t4 = lane & 3;          // fragment col group

    // B ldmatrix per-lane addressing
    const int t8 = lane >> 3;         // tile id 0..3
    const int rr = lane & 7;          // row within 8x8 tile
    const uint32_t b_row_off = (uint32_t)(wn + (t8 >> 1) * 8 + rr) * KC;
    const uint32_t b_kt = (uint32_t)(t8 & 1);

    // ---- B loader: 4 x cp16 per thread per chunk (512 threads, 2048 granules)
    auto load_B = [&](int stage, int c) {
        const uint32_t bs = sB0 + stage * B_STAGE;
        const size_t kbase = (size_t)c * KC;
        #pragma unroll
        for (int j = 0; j < 4; ++j) {
            int gid = j * 512 + tid;
            int row = gid >> 3;
            int gr  = gid & 7;
            uint32_t dst = bs + row * KC + (uint32_t)((gr ^ (row & 7)) << 4);
            cp16(dst, g_Wq + (size_t)(n0 + row) * D_IN + kbase + gr * 16);
        }
        cp_commit();
    };

    // ---- A fragment loader: chunk c, k-step ks -> a[2][4] packed s8
    // m16n8k32 A layout: reg0 row=g   k=t4*4..+3 ; reg1 row=g+8 ; reg2 k+16 ; reg3 both
    const float* xbase = X + (size_t)(m0 + wm + g) * D_IN + t4 * 4;
    auto ldA = [&](int c, int ks, uint32_t a[2][4]) {
        #pragma unroll
        for (int mf = 0; mf < 2; ++mf) {
            const float* p0 = xbase + (size_t)(mf * 16) * D_IN + c * KC + ks * 32;
            a[mf][0] = pk4(*(const uint4*)(p0));
            a[mf][1] = pk4(*(const uint4*)(p0 + (size_t)8 * D_IN));
            a[mf][2] = pk4(*(const uint4*)(p0 + 16));
            a[mf][3] = pk4(*(const uint4*)(p0 + (size_t)8 * D_IN + 16));
        }
    };

    int acc[2][8][4];
    #pragma unroll
    for (int mf = 0; mf < 2; ++mf)
        #pragma unroll
        for (int nf = 0; nf < 8; ++nf)
            #pragma unroll
            for (int q = 0; q < 4; ++q) acc[mf][nf][q] = 0;

    // ---- prologue
    uint32_t acur[2][4], anxt[2][4];
    ldA(0, 0, acur);
    load_B(0, 0);
    load_B(1, 1);

    for (int c = 0; c < NCHUNK; ++c) {
        if (c < NCHUNK - 1) cp_wait<1>();
        else                cp_wait<0>();
        __syncthreads();
        if (c + 2 < NCHUNK) load_B((c + 2) % 3, c + 2);

        const uint32_t b_s = sB0 + (c % 3) * B_STAGE;

        #pragma unroll
        for (int ks = 0; ks < 4; ++ks) {
            // prefetch next A fragments (global; no barrier dependence)
            if (ks < 3)               ldA(c, ks + 1, anxt);
            else if (c + 1 < NCHUNK)  ldA(c + 1, 0, anxt);

            uint32_t bb[4][4];
            #pragma unroll
            for (int np = 0; np < 4; ++np) {
                uint32_t g16 = (uint32_t)(2 * ks) + b_kt;
                ldsm4(bb[np], b_s + b_row_off + np * 16 * KC + ((g16 ^ rr) << 4));
            }
            #pragma unroll
            for (int mf = 0; mf < 2; ++mf)
                #pragma unroll
                for (int np = 0; np < 4; ++np) {
                    mma_s8(acc[mf][2 * np],     acur[mf], bb[np][0], bb[np][1]);
                    mma_s8(acc[mf][2 * np + 1], acur[mf], bb[np][2], bb[np][3]);
                }
            #pragma unroll
            for (int mf = 0; mf < 2; ++mf)
                #pragma unroll
                for (int q = 0; q < 4; ++q) acur[mf][q] = anxt[mf][q];
        }
    }

    // ---- epilogue: BN fold + fp32 store
    const int lr = lane >> 2;
    const int lc = (lane & 3) * 2;
    #pragma unroll
    for (int nf = 0; nf < 8; ++nf) {
        const int cn = n0 + wn + nf * 8 + lc;
        const float al0 = g_alpha[cn],     cb0 = g_cbias[cn];
        const float al1 = g_alpha[cn + 1], cb1 = g_cbias[cn + 1];
        #pragma unroll
        for (int mf = 0; mf < 2; ++mf) {
            const int r0 = m0 + wm + mf * 16 + lr;
            float2 v0, v1;
            v0.x = (float)acc[mf][nf][0] * al0 + cb0;
            v0.y = (float)acc[mf][nf][1] * al1 + cb1;
            v1.x = (float)acc[mf][nf][2] * al0 + cb0;
            v1.y = (float)acc[mf][nf][3] * al1 + cb1;
            *(float2*)(out + (size_t)r0 * D_H + cn) = v0;
            *(float2*)(out + (size_t)(r0 + 8) * D_H + cn) = v1;
        }
    }
}

// ---------------- launch ----------------
extern "C" void kernel_launch(void* const* d_in, const int* in_sizes, int n_in,
                              void* d_out, int out_size) {
    const float* X    = (const float*)d_in[0];
    const float* W    = (const float*)d_in[1];
    const float* b    = (const float*)d_in[2];
    const float* beta = (const float*)d_in[3];
    const float* mean = (const float*)d_in[4];
    const float* var  = (const float*)d_in[5];
    float* out = (float*)d_out;

    const int M = in_sizes[0] / D_IN;   // 32768

    dim3 pb(32, 8);
    dim3 pg(D_H / 32, D_IN / 32);
    qdbn_prep_kernel<<<pg, pb>>>(W, b, beta, mean, var);

    cudaFuncSetAttribute(qdbn_fused_kernel,
                         cudaFuncAttributeMaxDynamicSharedMemorySize, SMEM_DYN);
    dim3 grid(D_H / BN, M / BM);        // (2, 256)
    qdbn_fused_kernel<<<grid, 512, SMEM_DYN>>>(X, out);
}